// round 5
// baseline (speedup 1.0000x reference)
#include <cuda_runtime.h>
#include <cuda_bf16.h>
#include <math.h>

#define N_POINTS 8192
#define TI 1024            // i-tile per pair block
#define TJ 256             // j-tile per pair block
#define THREADS 256
#define IPT 4              // i's per thread
#define NB (N_POINTS / TJ) // 32 j-chunks
#define PAIR_TILES 144     // sum_{a=0}^{7} (32 - 4a)
#define GRID 148           // exactly one wave on 148 SMs

// Scratch: one slot per block, plus a completion counter. No f64 atomics.
__device__ double g_pair_partial[GRID];
__device__ float  g_s1_partial[GRID];
__device__ float  g_s2_partial[GRID];
__device__ int    g_done = 0;

__device__ __forceinline__ float frcp_approx(float x) {
    float y;
    asm("rcp.approx.f32 %0, %1;" : "=f"(y) : "f"(x));
    return y;
}

// Block reduce; full sum valid on thread 0 only. All threads must call.
__device__ __forceinline__ float block_reduce(float v) {
    #pragma unroll
    for (int off = 16; off > 0; off >>= 1)
        v += __shfl_xor_sync(0xFFFFFFFFu, v, off);
    __shared__ float warp_sums[8];
    int lane = threadIdx.x & 31;
    int wid  = threadIdx.x >> 5;
    if (lane == 0) warp_sums[wid] = v;
    __syncthreads();
    float s = 0.0f;
    if (wid == 0) {
        s = (lane < (THREADS >> 5)) ? warp_sums[lane] : 0.0f;
        #pragma unroll
        for (int off = 4; off > 0; off >>= 1)
            s += __shfl_xor_sync(0xFFFFFFFFu, s, off);
    }
    __syncthreads();   // safe reuse of warp_sums on next call
    return s;
}

__global__ void __launch_bounds__(THREADS)
main_kernel(const float2* __restrict__ pts,
            const float* __restrict__ pij,
            const int* __restrict__ ei,
            const int* __restrict__ ej,
            int n_edges,
            float* __restrict__ out) {
    int bid = blockIdx.x;
    int tid = threadIdx.x;

    // ---------------- pair phase (blocks 0..143) ----------------
    double pair_total = 0.0;
    if (bid < PAIR_TILES) {
        int rem = bid, a = 0;
        while (rem >= NB - 4 * a) { rem -= NB - 4 * a; a++; }
        int b = 4 * a + rem;
        bool masked = (b < 4 * a + 4);     // straddles the diagonal

        __shared__ float4 feat[TJ];
        int jBase = b * TJ;
        {
            float2 pj = pts[jBase + tid];
            feat[tid] = make_float4(
                -2.0f * pj.x, -2.0f * pj.y,
                fmaf(pj.x, pj.x, fmaf(pj.y, pj.y, 1.0f)), 0.0f);
        }
        __syncthreads();

        int iBase = a * TI;
        float xi[IPT], yi[IPT], ci[IPT];
        int   ii[IPT];
        #pragma unroll
        for (int k = 0; k < IPT; k++) {
            int i = iBase + tid + THREADS * k;
            float2 p = pts[i];
            xi[k] = p.x; yi[k] = p.y;
            ci[k] = fmaf(p.x, p.x, p.y * p.y);
            ii[k] = i;
        }

        float acc0 = 0.0f, acc1 = 0.0f;
        if (!masked) {
            #pragma unroll 8
            for (int jj = 0; jj < TJ; jj++) {
                float4 f = feat[jj];
                float d0 = fmaf(yi[0], f.y, fmaf(xi[0], f.x, f.z)) + ci[0];
                float d1 = fmaf(yi[1], f.y, fmaf(xi[1], f.x, f.z)) + ci[1];
                float d2 = fmaf(yi[2], f.y, fmaf(xi[2], f.x, f.z)) + ci[2];
                float d3 = fmaf(yi[3], f.y, fmaf(xi[3], f.x, f.z)) + ci[3];
                acc0 = fmaf(d0 + d1, frcp_approx(d0 * d1), acc0);
                acc1 = fmaf(d2 + d3, frcp_approx(d2 * d3), acc1);
            }
        } else {
            #pragma unroll 4
            for (int jj = 0; jj < TJ; jj++) {
                int j = jBase + jj;
                float4 f = feat[jj];
                float d0 = fmaf(yi[0], f.y, fmaf(xi[0], f.x, f.z)) + ci[0];
                float d1 = fmaf(yi[1], f.y, fmaf(xi[1], f.x, f.z)) + ci[1];
                float d2 = fmaf(yi[2], f.y, fmaf(xi[2], f.x, f.z)) + ci[2];
                float d3 = fmaf(yi[3], f.y, fmaf(xi[3], f.x, f.z)) + ci[3];
                d0 = (ii[0] < j) ? d0 : 1e12f;   // 1/1e12 ~ 0
                d1 = (ii[1] < j) ? d1 : 1e12f;
                d2 = (ii[2] < j) ? d2 : 1e12f;
                d3 = (ii[3] < j) ? d3 : 1e12f;
                acc0 = fmaf(d0 + d1, frcp_approx(d0 * d1), acc0);
                acc1 = fmaf(d2 + d3, frcp_approx(d2 * d3), acc1);
            }
        }
        float t = block_reduce(acc0 + acc1);
        if (tid == 0) pair_total = (double)t;
    }

    // ---------------- edge phase (all 148 blocks) ----------------
    float s1 = 0.0f, s2 = 0.0f;
    {
        int stride = GRID * THREADS;
        for (int e = bid * THREADS + tid; e < n_edges; e += stride) {
            int ia = ei[e];
            int ja = ej[e];
            float p = pij[e];
            float2 xa = pts[ia];
            float2 xb = pts[ja];
            float dx = xa.x - xb.x;
            float dy = xa.y - xb.y;
            float d = fmaf(dy, dy, fmaf(dx, dx, 2.0f));   // D + ||xi-xj||^2
            s1 += p * __logf(p * d);                      // p*(log p + log(2+d2))
            s2 += p;
        }
    }
    float t1 = block_reduce(s1);
    float t2 = block_reduce(s2);

    // ---------------- publish + last-block finish ----------------
    __shared__ int is_last;
    if (tid == 0) {
        g_pair_partial[bid] = pair_total;     // 0.0 for blocks 144..147
        g_s1_partial[bid]   = t1;
        g_s2_partial[bid]   = t2;
        __threadfence();
        int old = atomicAdd(&g_done, 1);
        is_last = (old == GRID - 1);
    }
    __syncthreads();

    if (is_last) {
        __threadfence();   // acquire side: make all partials visible
        double ps = 0.0;
        float f1 = 0.0f, f2 = 0.0f;
        if (tid < GRID) {
            ps = g_pair_partial[tid];
            f1 = g_s1_partial[tid];
            f2 = g_s2_partial[tid];
        }
        __shared__ double sd[THREADS];
        __shared__ float  sb1[THREADS];
        __shared__ float  sb2[THREADS];
        sd[tid] = ps; sb1[tid] = f1; sb2[tid] = f2;
        __syncthreads();
        for (int off = THREADS / 2; off > 0; off >>= 1) {
            if (tid < off) {
                sd[tid]  += sd[tid + off];
                sb1[tid] += sb1[tid + off];
                sb2[tid] += sb2[tid + off];
            }
            __syncthreads();
        }
        if (tid == 0) {
            double part = 2.0 * sd[0];   // diagonal cancels -n_diag exactly
            out[0] = (float)((double)sb1[0] + log(part) * (double)sb2[0]);
            g_done = 0;                  // reset for next graph replay
        }
    }
}

extern "C" void kernel_launch(void* const* d_in, const int* in_sizes, int n_in,
                              void* d_out, int out_size) {
    const float*  pij = (const float*)d_in[0];
    const int*    ei  = (const int*)d_in[1];   // jax w/o x64: int32 on device
    const int*    ej  = (const int*)d_in[2];
    const float2* pts = (const float2*)d_in[3];
    float*        out = (float*)d_out;
    int n_edges = in_sizes[0];

    main_kernel<<<GRID, THREADS>>>(pts, pij, ei, ej, n_edges, out);
}

// round 6
// speedup vs baseline: 1.2655x; 1.2655x over previous
#include <cuda_runtime.h>
#include <cuda_bf16.h>
#include <math.h>

#define N_POINTS 8192
#define TI 1024              // i-range per pair block
#define TJ 64                // j-range per pair block
#define THREADS 256
#define IPT 4                // i's per thread
#define NJC (N_POINTS / TJ)  // 128 j-chunks
#define PAIR_TILES 576       // sum_{a=0}^{7} (128 - 16a)
#define GRID PAIR_TILES

// Scratch: one slot per block + completion counter. (int atomic only — f64
// atomics to __device__ symbols trap on this setup; int counter verified R5.)
__device__ double g_pair_partial[GRID];
__device__ float  g_s1_partial[GRID];
__device__ float  g_s2_partial[GRID];
__device__ int    g_done = 0;

__device__ __forceinline__ float frcp_approx(float x) {
    float y;
    asm("rcp.approx.f32 %0, %1;" : "=f"(y) : "f"(x));
    return y;
}

// Block reduce; full sum valid on thread 0 only. All threads must call.
__device__ __forceinline__ float block_reduce(float v) {
    #pragma unroll
    for (int off = 16; off > 0; off >>= 1)
        v += __shfl_xor_sync(0xFFFFFFFFu, v, off);
    __shared__ float warp_sums[8];
    int lane = threadIdx.x & 31;
    int wid  = threadIdx.x >> 5;
    if (lane == 0) warp_sums[wid] = v;
    __syncthreads();
    float s = 0.0f;
    if (wid == 0) {
        s = (lane < (THREADS >> 5)) ? warp_sums[lane] : 0.0f;
        #pragma unroll
        for (int off = 4; off > 0; off >>= 1)
            s += __shfl_xor_sync(0xFFFFFFFFu, s, off);
    }
    __syncthreads();   // allow safe reuse of warp_sums
    return s;
}

__global__ void __launch_bounds__(THREADS)
main_kernel(const float2* __restrict__ pts,
            const float* __restrict__ pij,
            const int* __restrict__ ei,
            const int* __restrict__ ej,
            int n_edges,
            float* __restrict__ out) {
    int bid = blockIdx.x;
    int tid = threadIdx.x;

    // ---------------- pair phase: tile (a, b) ----------------
    // i in [1024a, 1024a+1024), j in [64b, 64b+64), b >= 16a.
    // Tiles with b < 16(a+1) straddle the diagonal -> masked.
    int rem = bid, a = 0;
    while (rem >= NJC - 16 * a) { rem -= NJC - 16 * a; a++; }
    int b = 16 * a + rem;
    bool masked = (b < 16 * (a + 1));

    __shared__ float4 feat[TJ];
    int jBase = b * TJ;
    if (tid < TJ) {
        float2 pj = pts[jBase + tid];
        feat[tid] = make_float4(
            -2.0f * pj.x, -2.0f * pj.y,
            fmaf(pj.x, pj.x, fmaf(pj.y, pj.y, 1.0f)), 0.0f);
    }
    __syncthreads();

    int iBase = a * TI;
    float xi[IPT], yi[IPT], ci[IPT];
    int   ii[IPT];
    #pragma unroll
    for (int k = 0; k < IPT; k++) {
        int i = iBase + tid + THREADS * k;
        float2 p = pts[i];
        xi[k] = p.x; yi[k] = p.y;
        ci[k] = fmaf(p.x, p.x, p.y * p.y);
        ii[k] = i;
    }

    float acc0 = 0.0f, acc1 = 0.0f;
    if (!masked) {
        #pragma unroll 8
        for (int jj = 0; jj < TJ; jj++) {
            float4 f = feat[jj];
            float d0 = fmaf(yi[0], f.y, fmaf(xi[0], f.x, f.z)) + ci[0];
            float d1 = fmaf(yi[1], f.y, fmaf(xi[1], f.x, f.z)) + ci[1];
            float d2 = fmaf(yi[2], f.y, fmaf(xi[2], f.x, f.z)) + ci[2];
            float d3 = fmaf(yi[3], f.y, fmaf(xi[3], f.x, f.z)) + ci[3];
            acc0 = fmaf(d0 + d1, frcp_approx(d0 * d1), acc0);
            acc1 = fmaf(d2 + d3, frcp_approx(d2 * d3), acc1);
        }
    } else {
        #pragma unroll 4
        for (int jj = 0; jj < TJ; jj++) {
            int j = jBase + jj;
            float4 f = feat[jj];
            float d0 = fmaf(yi[0], f.y, fmaf(xi[0], f.x, f.z)) + ci[0];
            float d1 = fmaf(yi[1], f.y, fmaf(xi[1], f.x, f.z)) + ci[1];
            float d2 = fmaf(yi[2], f.y, fmaf(xi[2], f.x, f.z)) + ci[2];
            float d3 = fmaf(yi[3], f.y, fmaf(xi[3], f.x, f.z)) + ci[3];
            d0 = (ii[0] < j) ? d0 : 1e12f;   // 1/1e12 contributes ~0
            d1 = (ii[1] < j) ? d1 : 1e12f;
            d2 = (ii[2] < j) ? d2 : 1e12f;
            d3 = (ii[3] < j) ? d3 : 1e12f;
            acc0 = fmaf(d0 + d1, frcp_approx(d0 * d1), acc0);
            acc1 = fmaf(d2 + d3, frcp_approx(d2 * d3), acc1);
        }
    }
    float pair_t = block_reduce(acc0 + acc1);

    // ---------------- edge phase (all blocks, grid-strided) ----------------
    float s1 = 0.0f, s2 = 0.0f;
    {
        int stride = GRID * THREADS;
        for (int e = bid * THREADS + tid; e < n_edges; e += stride) {
            int ia = ei[e];
            int ja = ej[e];
            float p = pij[e];
            float2 xa = pts[ia];
            float2 xb = pts[ja];
            float dx = xa.x - xb.x;
            float dy = xa.y - xb.y;
            float d = fmaf(dy, dy, fmaf(dx, dx, 2.0f));   // D + ||xi-xj||^2
            s1 += p * __logf(p * d);                      // p*(log p + log(2+d2))
            s2 += p;
        }
    }
    float t1 = block_reduce(s1);
    float t2 = block_reduce(s2);

    // ---------------- publish + last-block finish ----------------
    __shared__ int is_last;
    if (tid == 0) {
        g_pair_partial[bid] = (double)pair_t;
        g_s1_partial[bid]   = t1;
        g_s2_partial[bid]   = t2;
        __threadfence();
        int old = atomicAdd(&g_done, 1);
        is_last = (old == GRID - 1);
    }
    __syncthreads();

    if (is_last) {
        __threadfence();   // make all partials visible
        double ps = 0.0;
        float f1 = 0.0f, f2 = 0.0f;
        for (int k = tid; k < GRID; k += THREADS) {
            ps += g_pair_partial[k];
            f1 += g_s1_partial[k];
            f2 += g_s2_partial[k];
        }
        __shared__ double sd[THREADS];
        __shared__ float  sb1[THREADS];
        __shared__ float  sb2[THREADS];
        sd[tid] = ps; sb1[tid] = f1; sb2[tid] = f2;
        __syncthreads();
        for (int off = THREADS / 2; off > 0; off >>= 1) {
            if (tid < off) {
                sd[tid]  += sd[tid + off];
                sb1[tid] += sb1[tid + off];
                sb2[tid] += sb2[tid + off];
            }
            __syncthreads();
        }
        if (tid == 0) {
            double part = 2.0 * sd[0];   // diagonal cancels -n_diag exactly
            out[0] = (float)((double)sb1[0] + log(part) * (double)sb2[0]);
            g_done = 0;                  // reset for next graph replay
        }
    }
}

extern "C" void kernel_launch(void* const* d_in, const int* in_sizes, int n_in,
                              void* d_out, int out_size) {
    const float*  pij = (const float*)d_in[0];
    const int*    ei  = (const int*)d_in[1];   // jax w/o x64: int32 on device
    const int*    ej  = (const int*)d_in[2];
    const float2* pts = (const float2*)d_in[3];
    float*        out = (float*)d_out;
    int n_edges = in_sizes[0];

    main_kernel<<<GRID, THREADS>>>(pts, pij, ei, ej, n_edges, out);
}